// round 7
// baseline (speedup 1.0000x reference)
#include <cuda_runtime.h>
#include <math.h>

#define NMAX 100000
#define EMAX 1600000
#define FD 128
#define HD 128
#define CD 40
#define NLAY 4

// ---- static device scratch ----
// Invariant: g_cnt, g_stats, g_done are zero at entry of every kernel_launch
// call (zero at module load; each call re-zeroes them after use).
__device__ float g_xw[(size_t)NMAX * HD];
__device__ float g_agg[NLAY][(size_t)NMAX * HD];
__device__ float g_out[(size_t)NMAX * CD];
__device__ int   g_cnt[NMAX];
__device__ float g_dinv[NMAX];
__device__ int   g_off[NMAX + 1];
__device__ int   g_cur[NMAX];
__device__ int   g_csrc[EMAX];
__device__ float g_cval[EMAX];
__device__ float g_stats[NLAY][2 * HD];
__device__ float g_scale[NLAY][HD];
__device__ float g_sbias[NLAY][HD];
__device__ int   g_done[NLAY];

// ---- packed f32x2 helpers ----
__device__ __forceinline__ unsigned long long pk2(float lo, float hi) {
    unsigned long long r;
    asm("mov.b64 %0, {%1, %2};" : "=l"(r) : "f"(lo), "f"(hi));
    return r;
}
__device__ __forceinline__ void fma2(unsigned long long& d,
                                     unsigned long long a, unsigned long long b) {
    asm("fma.rn.f32x2 %0, %1, %2, %0;" : "+l"(d) : "l"(a), "l"(b));
}
__device__ __forceinline__ float2 up2(unsigned long long v) {
    float2 r;
    asm("mov.b64 {%0, %1}, %2;" : "=f"(r.x), "=f"(r.y) : "l"(v));
    return r;
}

// ---- tf32 helpers ----
__device__ __forceinline__ unsigned tf32_cvt(float f) {
    unsigned r;
    asm("cvt.rna.tf32.f32 %0, %1;" : "=r"(r) : "f"(f));
    return r;
}
__device__ __forceinline__ void mma_tf32(float* c, const unsigned* a, const unsigned* b) {
    asm("mma.sync.aligned.m16n8k8.row.col.f32.tf32.tf32.f32 "
        "{%0,%1,%2,%3}, {%4,%5,%6,%7}, {%8,%9}, {%0,%1,%2,%3};"
        : "+f"(c[0]), "+f"(c[1]), "+f"(c[2]), "+f"(c[3])
        : "r"(a[0]), "r"(a[1]), "r"(a[2]), "r"(a[3]), "r"(b[0]), "r"(b[1]));
}

// ---------------------------------------------------------------------------
__global__ void k_hist(const int* __restrict__ dst, int e) {
    int i = blockIdx.x * blockDim.x + threadIdx.x;
    if (i < e) atomicAdd(&g_cnt[dst[i]], 1);
}

__global__ void k_scan(int n) {
    __shared__ int sp[1024];
    int t = threadIdx.x;
    int chunk = (n + 1023) >> 10;
    int beg = t * chunk;
    int end = min(beg + chunk, n);
    int s = 0;
    for (int j = beg; j < end; j++) s += g_cnt[j];
    sp[t] = s;
    __syncthreads();
    for (int d = 1; d < 1024; d <<= 1) {
        int tmp = (t >= d) ? sp[t - d] : 0;
        __syncthreads();
        sp[t] += tmp;
        __syncthreads();
    }
    int base = sp[t] - s;
    for (int j = beg; j < end; j++) {
        int c = g_cnt[j];
        g_cnt[j] = 0;  // self-reset
        g_off[j] = base;
        g_cur[j] = base;
        g_dinv[j] = rsqrtf((float)c + 2.0f);
        base += c;
    }
    if (end == n) g_off[n] = base;
}

__global__ void k_fill(const int* __restrict__ src, const int* __restrict__ dst, int e) {
    int i = blockIdx.x * blockDim.x + threadIdx.x;
    if (i < e) {
        int d = dst[i];
        int s = src[i];
        int p = atomicAdd(&g_cur[d], 1);
        g_csrc[p] = s;
        g_cval[p] = g_dinv[s];
    }
}

// ---------------------------------------------------------------------------
// SGEMM via tf32 tensor cores, 3-term split. (unchanged from round 5/6)
__global__ __launch_bounds__(512, 1) void k_gemm(const float* __restrict__ x,
                                                 const float* __restrict__ W,
                                                 int layer, int n) {
    __shared__ __align__(16) float As[2][128][20];
    __shared__ __align__(16) float Bs[2][16][136];
    const float* A  = (layer == 0) ? x : g_agg[layer - 1];
    const float* sc = (layer > 0) ? g_scale[layer - 1] : 0;
    const float* sb = (layer > 0) ? g_sbias[layer - 1] : 0;
    int tid = threadIdx.x;
    int lane = tid & 31, wid = tid >> 5;
    int g4 = lane >> 2, t4 = lane & 3;
    int wr = (wid >> 2) * 32, wc = (wid & 3) * 32;
    int ar = tid >> 2, akq = (tid & 3) * 4;
    int bk = tid >> 5, bn0 = (tid & 31) * 4;
    int row0 = blockIdx.x * 128;
    int gr = row0 + ar;

    float acc[2][4][4];
#pragma unroll
    for (int mi = 0; mi < 2; mi++)
#pragma unroll
        for (int ni = 0; ni < 4; ni++)
#pragma unroll
            for (int q = 0; q < 4; q++) acc[mi][ni][q] = 0.f;

    float4 pa, pb;
    auto load_slab = [&](int s) {
        int k0 = s * 16;
        pa = make_float4(0.f, 0.f, 0.f, 0.f);
        if (gr < n) pa = *(const float4*)(A + (size_t)gr * HD + k0 + akq);
        if (layer > 0) {
            int kb = k0 + akq;
            pa.x = fmaxf(fmaf(pa.x, sc[kb + 0], sb[kb + 0]), 0.f);
            pa.y = fmaxf(fmaf(pa.y, sc[kb + 1], sb[kb + 1]), 0.f);
            pa.z = fmaxf(fmaf(pa.z, sc[kb + 2], sb[kb + 2]), 0.f);
            pa.w = fmaxf(fmaf(pa.w, sc[kb + 3], sb[kb + 3]), 0.f);
        }
        pb = *(const float4*)(W + (size_t)(k0 + bk) * HD + bn0);
    };
    auto store_slab = [&](int buf) {
        *(float4*)&As[buf][ar][akq] = pa;
        *(float4*)&Bs[buf][bk][bn0] = pb;
    };

    load_slab(0);
    store_slab(0);
    __syncthreads();

#pragma unroll
    for (int ks = 0; ks < 8; ks++) {
        int buf = ks & 1;
        if (ks < 7) load_slab(ks + 1);
#pragma unroll
        for (int kk = 0; kk < 2; kk++) {
            int kb = kk * 8;
            float af[2][4], bf[4][2];
#pragma unroll
            for (int mi = 0; mi < 2; mi++) {
                int m0 = wr + mi * 16 + g4;
                af[mi][0] = As[buf][m0][kb + t4];
                af[mi][1] = As[buf][m0 + 8][kb + t4];
                af[mi][2] = As[buf][m0][kb + 4 + t4];
                af[mi][3] = As[buf][m0 + 8][kb + 4 + t4];
            }
#pragma unroll
            for (int ni = 0; ni < 4; ni++) {
                int nn = wc + ni * 8 + g4;
                bf[ni][0] = Bs[buf][kb + t4][nn];
                bf[ni][1] = Bs[buf][kb + 4 + t4][nn];
            }
            unsigned ahi[2][4], bhi[4][2];
#pragma unroll
            for (int mi = 0; mi < 2; mi++)
#pragma unroll
                for (int q = 0; q < 4; q++) ahi[mi][q] = tf32_cvt(af[mi][q]);
#pragma unroll
            for (int ni = 0; ni < 4; ni++) {
                bhi[ni][0] = tf32_cvt(bf[ni][0]);
                bhi[ni][1] = tf32_cvt(bf[ni][1]);
            }
#pragma unroll
            for (int mi = 0; mi < 2; mi++)
#pragma unroll
                for (int ni = 0; ni < 4; ni++)
                    mma_tf32(acc[mi][ni], ahi[mi], bhi[ni]);
            unsigned blo[4][2];
#pragma unroll
            for (int ni = 0; ni < 4; ni++) {
                blo[ni][0] = tf32_cvt(bf[ni][0] - __uint_as_float(bhi[ni][0]));
                blo[ni][1] = tf32_cvt(bf[ni][1] - __uint_as_float(bhi[ni][1]));
            }
#pragma unroll
            for (int mi = 0; mi < 2; mi++)
#pragma unroll
                for (int ni = 0; ni < 4; ni++)
                    mma_tf32(acc[mi][ni], ahi[mi], blo[ni]);
            unsigned alo[2][4];
#pragma unroll
            for (int mi = 0; mi < 2; mi++)
#pragma unroll
                for (int q = 0; q < 4; q++)
                    alo[mi][q] = tf32_cvt(af[mi][q] - __uint_as_float(ahi[mi][q]));
#pragma unroll
            for (int mi = 0; mi < 2; mi++)
#pragma unroll
                for (int ni = 0; ni < 4; ni++)
                    mma_tf32(acc[mi][ni], alo[mi], bhi[ni]);
        }
        if (ks < 7) {
            store_slab(buf ^ 1);
            __syncthreads();
        }
    }
#pragma unroll
    for (int mi = 0; mi < 2; mi++) {
#pragma unroll
        for (int ni = 0; ni < 4; ni++) {
            int r = row0 + wr + mi * 16 + g4;
            int c = wc + ni * 8 + t4 * 2;
            if (r < n)
                *(float2*)(g_xw + (size_t)r * HD + c) =
                    make_float2(acc[mi][ni][0], acc[mi][ni][1]);
            if (r + 8 < n)
                *(float2*)(g_xw + (size_t)(r + 8) * HD + c) =
                    make_float2(acc[mi][ni][2], acc[mi][ni][3]);
        }
    }
}

// ---------------------------------------------------------------------------
// Per-layer class head: T = outs[layer] @ fc_w[layer]  (K=128, N=40).
// layer==0: g_out = T (A = x). 0<layer<NLAY: g_out += T (A = relu_bn(g_agg[l-1])).
// layer==NLAY: out = log_softmax(g_out + T + sum_bias)  (final, writes d_out).
// 256 threads = 8 warps; warp = 32 rows x 40 cols; tf32 3-pass split.
__global__ __launch_bounds__(256, 2) void k_head(const float* __restrict__ x,
                                                 const float* __restrict__ fw,
                                                 const float* __restrict__ fb,
                                                 float* __restrict__ outp,
                                                 int layer, int n) {
    __shared__ __align__(16) float As[2][256][20];
    __shared__ __align__(16) float Bs[2][16][40];
    __shared__ float bsum[40];
    const float* A  = (layer == 0) ? x : g_agg[layer - 1];
    const float* sc = (layer > 0) ? g_scale[layer - 1] : 0;
    const float* sb = (layer > 0) ? g_sbias[layer - 1] : 0;
    int tid = threadIdx.x;
    int lane = tid & 31, wid = tid >> 5;
    int g4 = lane >> 2, t4 = lane & 3;
    int wr = wid * 32;
    int row0 = blockIdx.x * 256;
    int gr = row0 + tid;                 // staging: one row per thread
    bool bldr = (tid < 160);
    int bkr = tid / 10, bnc = (tid % 10) * 4;

    if (layer == NLAY && tid < 40) {
        float b = 0.f;
        for (int i = 0; i < NLAY + 1; i++) b += fb[i * CD + tid];
        bsum[tid] = b;
    }

    float acc[2][5][4];
#pragma unroll
    for (int mi = 0; mi < 2; mi++)
#pragma unroll
        for (int ni = 0; ni < 5; ni++)
#pragma unroll
            for (int q = 0; q < 4; q++) acc[mi][ni][q] = 0.f;

    float4 pa[4];
    float4 pbv;
    auto load_slab = [&](int s) {
        int k0 = s * 16;
#pragma unroll
        for (int h = 0; h < 4; h++) pa[h] = make_float4(0.f, 0.f, 0.f, 0.f);
        if (gr < n) {
#pragma unroll
            for (int h = 0; h < 4; h++)
                pa[h] = *(const float4*)(A + (size_t)gr * HD + k0 + h * 4);
        }
        if (layer > 0) {
#pragma unroll
            for (int h = 0; h < 4; h++) {
                int kk = k0 + h * 4;
                float* p = (float*)&pa[h];
                p[0] = fmaxf(fmaf(p[0], sc[kk + 0], sb[kk + 0]), 0.f);
                p[1] = fmaxf(fmaf(p[1], sc[kk + 1], sb[kk + 1]), 0.f);
                p[2] = fmaxf(fmaf(p[2], sc[kk + 2], sb[kk + 2]), 0.f);
                p[3] = fmaxf(fmaf(p[3], sc[kk + 3], sb[kk + 3]), 0.f);
            }
        }
        if (bldr)
            pbv = *(const float4*)(fw + ((size_t)layer * HD + k0 + bkr) * CD + bnc);
    };
    auto store_slab = [&](int buf) {
#pragma unroll
        for (int h = 0; h < 4; h++) *(float4*)&As[buf][tid][h * 4] = pa[h];
        if (bldr) *(float4*)&Bs[buf][bkr][bnc] = pbv;
    };

    load_slab(0);
    store_slab(0);
    __syncthreads();

#pragma unroll
    for (int ks = 0; ks < 8; ks++) {
        int buf = ks & 1;
        if (ks < 7) load_slab(ks + 1);
#pragma unroll
        for (int kk = 0; kk < 2; kk++) {
            int kb = kk * 8;
            float af[2][4], bf[5][2];
#pragma unroll
            for (int mi = 0; mi < 2; mi++) {
                int m0 = wr + mi * 16 + g4;
                af[mi][0] = As[buf][m0][kb + t4];
                af[mi][1] = As[buf][m0 + 8][kb + t4];
                af[mi][2] = As[buf][m0][kb + 4 + t4];
                af[mi][3] = As[buf][m0 + 8][kb + 4 + t4];
            }
#pragma unroll
            for (int ni = 0; ni < 5; ni++) {
                int nn = ni * 8 + g4;
                bf[ni][0] = Bs[buf][kb + t4][nn];
                bf[ni][1] = Bs[buf][kb + 4 + t4][nn];
            }
            unsigned ahi[2][4], bhi[5][2];
#pragma unroll
            for (int mi = 0; mi < 2; mi++)
#pragma unroll
                for (int q = 0; q < 4; q++) ahi[mi][q] = tf32_cvt(af[mi][q]);
#pragma unroll
            for (int ni = 0; ni < 5; ni++) {
                bhi[ni][0] = tf32_cvt(bf[ni][0]);
                bhi[ni][1] = tf32_cvt(bf[ni][1]);
            }
#pragma unroll
            for (int mi = 0; mi < 2; mi++)
#pragma unroll
                for (int ni = 0; ni < 5; ni++)
                    mma_tf32(acc[mi][ni], ahi[mi], bhi[ni]);
            unsigned blo[5][2];
#pragma unroll
            for (int ni = 0; ni < 5; ni++) {
                blo[ni][0] = tf32_cvt(bf[ni][0] - __uint_as_float(bhi[ni][0]));
                blo[ni][1] = tf32_cvt(bf[ni][1] - __uint_as_float(bhi[ni][1]));
            }
#pragma unroll
            for (int mi = 0; mi < 2; mi++)
#pragma unroll
                for (int ni = 0; ni < 5; ni++)
                    mma_tf32(acc[mi][ni], ahi[mi], blo[ni]);
            unsigned alo[2][4];
#pragma unroll
            for (int mi = 0; mi < 2; mi++)
#pragma unroll
                for (int q = 0; q < 4; q++)
                    alo[mi][q] = tf32_cvt(af[mi][q] - __uint_as_float(ahi[mi][q]));
#pragma unroll
            for (int mi = 0; mi < 2; mi++)
#pragma unroll
                for (int ni = 0; ni < 5; ni++)
                    mma_tf32(acc[mi][ni], alo[mi], bhi[ni]);
        }
        if (ks < 7) {
            store_slab(buf ^ 1);
            __syncthreads();
        }
    }

    // epilogue
#pragma unroll
    for (int mi = 0; mi < 2; mi++) {
#pragma unroll
        for (int half = 0; half < 2; half++) {
            int r = row0 + wr + mi * 16 + half * 8 + g4;
            float v[5][2];
#pragma unroll
            for (int ni = 0; ni < 5; ni++) {
                v[ni][0] = acc[mi][ni][half * 2 + 0];
                v[ni][1] = acc[mi][ni][half * 2 + 1];
            }
            if (layer == 0) {
                if (r < n) {
#pragma unroll
                    for (int ni = 0; ni < 5; ni++)
                        *(float2*)(g_out + (size_t)r * CD + ni * 8 + t4 * 2) =
                            make_float2(v[ni][0], v[ni][1]);
                }
            } else if (layer < NLAY) {
                if (r < n) {
#pragma unroll
                    for (int ni = 0; ni < 5; ni++) {
                        float2* p = (float2*)(g_out + (size_t)r * CD + ni * 8 + t4 * 2);
                        float2 o = *p;
                        *p = make_float2(o.x + v[ni][0], o.y + v[ni][1]);
                    }
                }
            } else {
                // final: add g_out + bias, log_softmax over 40 cols (quad shfl)
#pragma unroll
                for (int ni = 0; ni < 5; ni++) {
                    int c = ni * 8 + t4 * 2;
                    float2 o = make_float2(0.f, 0.f);
                    if (r < n) o = *(const float2*)(g_out + (size_t)r * CD + c);
                    v[ni][0] += o.x + bsum[c];
                    v[ni][1] += o.y + bsum[c + 1];
                }
                float mx = v[0][0];
#pragma unroll
                for (int ni = 0; ni < 5; ni++) {
                    mx = fmaxf(mx, v[ni][0]);
                    mx = fmaxf(mx, v[ni][1]);
                }
                mx = fmaxf(mx, __shfl_xor_sync(0xffffffffu, mx, 1));
                mx = fmaxf(mx, __shfl_xor_sync(0xffffffffu, mx, 2));
                float s = 0.f;
#pragma unroll
                for (int ni = 0; ni < 5; ni++)
                    s += expf(v[ni][0] - mx) + expf(v[ni][1] - mx);
                s += __shfl_xor_sync(0xffffffffu, s, 1);
                s += __shfl_xor_sync(0xffffffffu, s, 2);
                float ls = mx + logf(s);
                if (r < n) {
#pragma unroll
                    for (int ni = 0; ni < 5; ni++)
                        *(float2*)(outp + (size_t)r * CD + ni * 8 + t4 * 2) =
                            make_float2(v[ni][0] - ls, v[ni][1] - ls);
                }
            }
        }
    }
}

// ---------------------------------------------------------------------------
// Aggregation (unchanged): warp per node; lane owns 4 columns; unroll-8.
__global__ __launch_bounds__(256) void k_agg(int layer, const float* __restrict__ convb,
                                             const float* __restrict__ bn_g,
                                             const float* __restrict__ bn_b, int n) {
    __shared__ float s_sum[128], s_sq[128];
    __shared__ int s_last;
    int tid = threadIdx.x;
    if (tid < 128) { s_sum[tid] = 0.f; s_sq[tid] = 0.f; }
    __syncthreads();

    int lane = tid & 31;
    int warp = tid >> 5;
    int c4 = lane * 4;
    float4 b4 = *(const float4*)(convb + c4);
    float* out = g_agg[layer];

    int gw = blockIdx.x * 8 + warp;
    int nw = gridDim.x * 8;

    float ls0 = 0.f, ls1 = 0.f, ls2 = 0.f, ls3 = 0.f;
    float lq0 = 0.f, lq1 = 0.f, lq2 = 0.f, lq3 = 0.f;

    for (int v = gw; v < n; v += nw) {
        int r0 = g_off[v], r1 = g_off[v + 1];
        float dv = g_dinv[v];
        unsigned long long p0 = 0ull, p1 = 0ull;
        int j = r0;
        for (; j + 7 < r1; j += 8) {
            int   si[8];
            float wi[8];
#pragma unroll
            for (int u = 0; u < 8; u++) { si[u] = g_csrc[j + u]; wi[u] = g_cval[j + u]; }
            float4 xv[8];
#pragma unroll
            for (int u = 0; u < 8; u++)
                xv[u] = *(const float4*)(g_xw + (size_t)si[u] * HD + c4);
#pragma unroll
            for (int u = 0; u < 8; u++) {
                unsigned long long wd = pk2(wi[u], wi[u]);
                fma2(p0, wd, pk2(xv[u].x, xv[u].y));
                fma2(p1, wd, pk2(xv[u].z, xv[u].w));
            }
        }
        for (; j < r1; j++) {
            int s0 = g_csrc[j];
            float w0 = g_cval[j];
            float4 x0 = *(const float4*)(g_xw + (size_t)s0 * HD + c4);
            unsigned long long wd0 = pk2(w0, w0);
            fma2(p0, wd0, pk2(x0.x, x0.y)); fma2(p1, wd0, pk2(x0.z, x0.w));
        }
        float2 e0 = up2(p0), e1 = up2(p1);
        float4 xs = *(const float4*)(g_xw + (size_t)v * HD + c4);
        float t2 = 2.f * dv * dv;
        float a0 = fmaf(dv, e0.x, fmaf(t2, xs.x, b4.x));
        float a1 = fmaf(dv, e0.y, fmaf(t2, xs.y, b4.y));
        float a2 = fmaf(dv, e1.x, fmaf(t2, xs.z, b4.z));
        float a3 = fmaf(dv, e1.y, fmaf(t2, xs.w, b4.w));
        *(float4*)(out + (size_t)v * HD + c4) = make_float4(a0, a1, a2, a3);
        ls0 += a0; ls1 += a1; ls2 += a2; ls3 += a3;
        lq0 = fmaf(a0, a0, lq0); lq1 = fmaf(a1, a1, lq1);
        lq2 = fmaf(a2, a2, lq2); lq3 = fmaf(a3, a3, lq3);
    }
    atomicAdd(&s_sum[c4 + 0], ls0); atomicAdd(&s_sum[c4 + 1], ls1);
    atomicAdd(&s_sum[c4 + 2], ls2); atomicAdd(&s_sum[c4 + 3], ls3);
    atomicAdd(&s_sq[c4 + 0], lq0);  atomicAdd(&s_sq[c4 + 1], lq1);
    atomicAdd(&s_sq[c4 + 2], lq2);  atomicAdd(&s_sq[c4 + 3], lq3);
    __syncthreads();
    if (tid < 128) {
        atomicAdd(&g_stats[layer][tid], s_sum[tid]);
        atomicAdd(&g_stats[layer][128 + tid], s_sq[tid]);
    }
    __threadfence();
    __syncthreads();
    if (tid == 0) {
        int p = atomicAdd(&g_done[layer], 1);
        s_last = (p == (int)gridDim.x - 1);
    }
    __syncthreads();
    if (s_last && tid < 128) {
        __threadfence();
        float sum = g_stats[layer][tid];
        float sq  = g_stats[layer][tid + 128];
        g_stats[layer][tid] = 0.f;
        g_stats[layer][tid + 128] = 0.f;
        if (tid == 0) g_done[layer] = 0;
        float inv_n = 1.0f / (float)n;
        float mean = sum * inv_n;
        float var  = fmaxf(sq * inv_n - mean * mean, 0.f);
        float s = bn_g[layer * HD + tid] * rsqrtf(var + 1e-5f);
        g_scale[layer][tid] = s;
        g_sbias[layer][tid] = bn_b[layer * HD + tid] - mean * s;
    }
}

// ---------------------------------------------------------------------------
extern "C" void kernel_launch(void* const* d_in, const int* in_sizes, int n_in,
                              void* d_out, int out_size) {
    const float* x      = (const float*)d_in[0];
    const int*   ei     = (const int*)d_in[1];
    const float* conv_w = (const float*)d_in[2];
    const float* conv_b = (const float*)d_in[3];
    const float* bn_g   = (const float*)d_in[4];
    const float* bn_b   = (const float*)d_in[5];
    const float* fc_w   = (const float*)d_in[6];
    const float* fc_b   = (const float*)d_in[7];
    int n = in_sizes[0] / FD;
    int e = in_sizes[1] / 2;
    const int* src = ei;
    const int* dst = ei + e;

    k_hist<<<(e + 255) / 256, 256>>>(dst, e);
    k_scan<<<1, 1024>>>(n);
    k_fill<<<(e + 255) / 256, 256>>>(src, dst, e);

    int gblocks = (n + 127) / 128;
    int hblocks = (n + 255) / 256;
    for (int l = 0; l < NLAY; l++) {
        k_gemm<<<gblocks, 512>>>(x, conv_w + (size_t)l * FD * HD, l, n);
        k_head<<<hblocks, 256>>>(x, fc_w, fc_b, (float*)d_out, l, n);
        k_agg<<<1184, 256>>>(l, conv_b + (size_t)l * HD, bn_g, bn_b, n);
    }
    k_head<<<hblocks, 256>>>(x, fc_w, fc_b, (float*)d_out, NLAY, n);
}

// round 8
// speedup vs baseline: 1.0471x; 1.0471x over previous
#include <cuda_runtime.h>
#include <math.h>

#define NMAX 100000
#define EMAX 1600000
#define FD 128
#define HD 128
#define CD 40
#define NLAY 4

// ---- static device scratch ----
// Invariant: g_cnt, g_stats, g_done are zero at entry of every kernel_launch
// call (zero at module load; each call re-zeroes them after use).
__device__ float g_xw[(size_t)NMAX * HD];
__device__ float g_agg[NLAY][(size_t)NMAX * HD];
__device__ int   g_cnt[NMAX];
__device__ float g_dinv[NMAX];
__device__ int   g_off[NMAX + 1];
__device__ int   g_cur[NMAX];
__device__ int   g_csrc[EMAX];
__device__ float g_cval[EMAX];
__device__ float g_stats[NLAY][2 * HD];
__device__ float g_scale[NLAY][HD];
__device__ float g_sbias[NLAY][HD];
__device__ int   g_done[NLAY];

// ---- packed f32x2 helpers ----
__device__ __forceinline__ unsigned long long pk2(float lo, float hi) {
    unsigned long long r;
    asm("mov.b64 %0, {%1, %2};" : "=l"(r) : "f"(lo), "f"(hi));
    return r;
}
__device__ __forceinline__ void fma2(unsigned long long& d,
                                     unsigned long long a, unsigned long long b) {
    asm("fma.rn.f32x2 %0, %1, %2, %0;" : "+l"(d) : "l"(a), "l"(b));
}
__device__ __forceinline__ float2 up2(unsigned long long v) {
    float2 r;
    asm("mov.b64 {%0, %1}, %2;" : "=f"(r.x), "=f"(r.y) : "l"(v));
    return r;
}

// ---- tf32 helpers ----
__device__ __forceinline__ unsigned tf32_cvt(float f) {
    unsigned r;
    asm("cvt.rna.tf32.f32 %0, %1;" : "=r"(r) : "f"(f));
    return r;
}
__device__ __forceinline__ void mma_tf32(float* c, const unsigned* a, const unsigned* b) {
    asm("mma.sync.aligned.m16n8k8.row.col.f32.tf32.tf32.f32 "
        "{%0,%1,%2,%3}, {%4,%5,%6,%7}, {%8,%9}, {%0,%1,%2,%3};"
        : "+f"(c[0]), "+f"(c[1]), "+f"(c[2]), "+f"(c[3])
        : "r"(a[0]), "r"(a[1]), "r"(a[2]), "r"(a[3]), "r"(b[0]), "r"(b[1]));
}

// ---------------------------------------------------------------------------
__global__ void k_hist(const int* __restrict__ dst, int e) {
    int i = blockIdx.x * blockDim.x + threadIdx.x;
    if (i < e) atomicAdd(&g_cnt[dst[i]], 1);
}

__global__ void k_scan(int n) {
    __shared__ int sp[1024];
    int t = threadIdx.x;
    int chunk = (n + 1023) >> 10;
    int beg = t * chunk;
    int end = min(beg + chunk, n);
    int s = 0;
    for (int j = beg; j < end; j++) s += g_cnt[j];
    sp[t] = s;
    __syncthreads();
    for (int d = 1; d < 1024; d <<= 1) {
        int tmp = (t >= d) ? sp[t - d] : 0;
        __syncthreads();
        sp[t] += tmp;
        __syncthreads();
    }
    int base = sp[t] - s;
    for (int j = beg; j < end; j++) {
        int c = g_cnt[j];
        g_cnt[j] = 0;  // self-reset
        g_off[j] = base;
        g_cur[j] = base;
        g_dinv[j] = rsqrtf((float)c + 2.0f);
        base += c;
    }
    if (end == n) g_off[n] = base;
}

__global__ void k_fill(const int* __restrict__ src, const int* __restrict__ dst, int e) {
    int i = blockIdx.x * blockDim.x + threadIdx.x;
    if (i < e) {
        int d = dst[i];
        int s = src[i];
        int p = atomicAdd(&g_cur[d], 1);
        g_csrc[p] = s;
        g_cval[p] = g_dinv[s];
    }
}

// ---------------------------------------------------------------------------
// SGEMM via tf32 tensor cores, 3-term split (fp32-class accuracy; feeds BN
// statistics so precision kept here). Unchanged from rounds 5-7.
__global__ __launch_bounds__(512, 1) void k_gemm(const float* __restrict__ x,
                                                 const float* __restrict__ W,
                                                 int layer, int n) {
    __shared__ __align__(16) float As[2][128][20];
    __shared__ __align__(16) float Bs[2][16][136];
    const float* A  = (layer == 0) ? x : g_agg[layer - 1];
    const float* sc = (layer > 0) ? g_scale[layer - 1] : 0;
    const float* sb = (layer > 0) ? g_sbias[layer - 1] : 0;
    int tid = threadIdx.x;
    int lane = tid & 31, wid = tid >> 5;
    int g4 = lane >> 2, t4 = lane & 3;
    int wr = (wid >> 2) * 32, wc = (wid & 3) * 32;
    int ar = tid >> 2, akq = (tid & 3) * 4;
    int bk = tid >> 5, bn0 = (tid & 31) * 4;
    int row0 = blockIdx.x * 128;
    int gr = row0 + ar;

    float acc[2][4][4];
#pragma unroll
    for (int mi = 0; mi < 2; mi++)
#pragma unroll
        for (int ni = 0; ni < 4; ni++)
#pragma unroll
            for (int q = 0; q < 4; q++) acc[mi][ni][q] = 0.f;

    float4 pa, pb;
    auto load_slab = [&](int s) {
        int k0 = s * 16;
        pa = make_float4(0.f, 0.f, 0.f, 0.f);
        if (gr < n) pa = *(const float4*)(A + (size_t)gr * HD + k0 + akq);
        if (layer > 0) {
            int kb = k0 + akq;
            pa.x = fmaxf(fmaf(pa.x, sc[kb + 0], sb[kb + 0]), 0.f);
            pa.y = fmaxf(fmaf(pa.y, sc[kb + 1], sb[kb + 1]), 0.f);
            pa.z = fmaxf(fmaf(pa.z, sc[kb + 2], sb[kb + 2]), 0.f);
            pa.w = fmaxf(fmaf(pa.w, sc[kb + 3], sb[kb + 3]), 0.f);
        }
        pb = *(const float4*)(W + (size_t)(k0 + bk) * HD + bn0);
    };
    auto store_slab = [&](int buf) {
        *(float4*)&As[buf][ar][akq] = pa;
        *(float4*)&Bs[buf][bk][bn0] = pb;
    };

    load_slab(0);
    store_slab(0);
    __syncthreads();

#pragma unroll
    for (int ks = 0; ks < 8; ks++) {
        int buf = ks & 1;
        if (ks < 7) load_slab(ks + 1);
#pragma unroll
        for (int kk = 0; kk < 2; kk++) {
            int kb = kk * 8;
            float af[2][4], bf[4][2];
#pragma unroll
            for (int mi = 0; mi < 2; mi++) {
                int m0 = wr + mi * 16 + g4;
                af[mi][0] = As[buf][m0][kb + t4];
                af[mi][1] = As[buf][m0 + 8][kb + t4];
                af[mi][2] = As[buf][m0][kb + 4 + t4];
                af[mi][3] = As[buf][m0 + 8][kb + 4 + t4];
            }
#pragma unroll
            for (int ni = 0; ni < 4; ni++) {
                int nn = wc + ni * 8 + g4;
                bf[ni][0] = Bs[buf][kb + t4][nn];
                bf[ni][1] = Bs[buf][kb + 4 + t4][nn];
            }
            unsigned ahi[2][4], bhi[4][2];
#pragma unroll
            for (int mi = 0; mi < 2; mi++)
#pragma unroll
                for (int q = 0; q < 4; q++) ahi[mi][q] = tf32_cvt(af[mi][q]);
#pragma unroll
            for (int ni = 0; ni < 4; ni++) {
                bhi[ni][0] = tf32_cvt(bf[ni][0]);
                bhi[ni][1] = tf32_cvt(bf[ni][1]);
            }
#pragma unroll
            for (int mi = 0; mi < 2; mi++)
#pragma unroll
                for (int ni = 0; ni < 4; ni++)
                    mma_tf32(acc[mi][ni], ahi[mi], bhi[ni]);
            unsigned blo[4][2];
#pragma unroll
            for (int ni = 0; ni < 4; ni++) {
                blo[ni][0] = tf32_cvt(bf[ni][0] - __uint_as_float(bhi[ni][0]));
                blo[ni][1] = tf32_cvt(bf[ni][1] - __uint_as_float(bhi[ni][1]));
            }
#pragma unroll
            for (int mi = 0; mi < 2; mi++)
#pragma unroll
                for (int ni = 0; ni < 4; ni++)
                    mma_tf32(acc[mi][ni], ahi[mi], blo[ni]);
            unsigned alo[2][4];
#pragma unroll
            for (int mi = 0; mi < 2; mi++)
#pragma unroll
                for (int q = 0; q < 4; q++)
                    alo[mi][q] = tf32_cvt(af[mi][q] - __uint_as_float(ahi[mi][q]));
#pragma unroll
            for (int mi = 0; mi < 2; mi++)
#pragma unroll
                for (int ni = 0; ni < 4; ni++)
                    mma_tf32(acc[mi][ni], alo[mi], bhi[ni]);
        }
        if (ks < 7) {
            store_slab(buf ^ 1);
            __syncthreads();
        }
    }
#pragma unroll
    for (int mi = 0; mi < 2; mi++) {
#pragma unroll
        for (int ni = 0; ni < 4; ni++) {
            int r = row0 + wr + mi * 16 + g4;
            int c = wc + ni * 8 + t4 * 2;
            if (r < n)
                *(float2*)(g_xw + (size_t)r * HD + c) =
                    make_float2(acc[mi][ni][0], acc[mi][ni][1]);
            if (r + 8 < n)
                *(float2*)(g_xw + (size_t)(r + 8) * HD + c) =
                    make_float2(acc[mi][ni][2], acc[mi][ni][3]);
        }
    }
}

// ---------------------------------------------------------------------------
// Aggregation (unchanged): warp per node; lane owns 4 columns; unroll-8.
__global__ __launch_bounds__(256) void k_agg(int layer, const float* __restrict__ convb,
                                             const float* __restrict__ bn_g,
                                             const float* __restrict__ bn_b, int n) {
    __shared__ float s_sum[128], s_sq[128];
    __shared__ int s_last;
    int tid = threadIdx.x;
    if (tid < 128) { s_sum[tid] = 0.f; s_sq[tid] = 0.f; }
    __syncthreads();

    int lane = tid & 31;
    int warp = tid >> 5;
    int c4 = lane * 4;
    float4 b4 = *(const float4*)(convb + c4);
    float* out = g_agg[layer];

    int gw = blockIdx.x * 8 + warp;
    int nw = gridDim.x * 8;

    float ls0 = 0.f, ls1 = 0.f, ls2 = 0.f, ls3 = 0.f;
    float lq0 = 0.f, lq1 = 0.f, lq2 = 0.f, lq3 = 0.f;

    for (int v = gw; v < n; v += nw) {
        int r0 = g_off[v], r1 = g_off[v + 1];
        float dv = g_dinv[v];
        unsigned long long p0 = 0ull, p1 = 0ull;
        int j = r0;
        for (; j + 7 < r1; j += 8) {
            int   si[8];
            float wi[8];
#pragma unroll
            for (int u = 0; u < 8; u++) { si[u] = g_csrc[j + u]; wi[u] = g_cval[j + u]; }
            float4 xv[8];
#pragma unroll
            for (int u = 0; u < 8; u++)
                xv[u] = *(const float4*)(g_xw + (size_t)si[u] * HD + c4);
#pragma unroll
            for (int u = 0; u < 8; u++) {
                unsigned long long wd = pk2(wi[u], wi[u]);
                fma2(p0, wd, pk2(xv[u].x, xv[u].y));
                fma2(p1, wd, pk2(xv[u].z, xv[u].w));
            }
        }
        for (; j < r1; j++) {
            int s0 = g_csrc[j];
            float w0 = g_cval[j];
            float4 x0 = *(const float4*)(g_xw + (size_t)s0 * HD + c4);
            unsigned long long wd0 = pk2(w0, w0);
            fma2(p0, wd0, pk2(x0.x, x0.y)); fma2(p1, wd0, pk2(x0.z, x0.w));
        }
        float2 e0 = up2(p0), e1 = up2(p1);
        float4 xs = *(const float4*)(g_xw + (size_t)v * HD + c4);
        float t2 = 2.f * dv * dv;
        float a0 = fmaf(dv, e0.x, fmaf(t2, xs.x, b4.x));
        float a1 = fmaf(dv, e0.y, fmaf(t2, xs.y, b4.y));
        float a2 = fmaf(dv, e1.x, fmaf(t2, xs.z, b4.z));
        float a3 = fmaf(dv, e1.y, fmaf(t2, xs.w, b4.w));
        *(float4*)(out + (size_t)v * HD + c4) = make_float4(a0, a1, a2, a3);
        ls0 += a0; ls1 += a1; ls2 += a2; ls3 += a3;
        lq0 = fmaf(a0, a0, lq0); lq1 = fmaf(a1, a1, lq1);
        lq2 = fmaf(a2, a2, lq2); lq3 = fmaf(a3, a3, lq3);
    }
    atomicAdd(&s_sum[c4 + 0], ls0); atomicAdd(&s_sum[c4 + 1], ls1);
    atomicAdd(&s_sum[c4 + 2], ls2); atomicAdd(&s_sum[c4 + 3], ls3);
    atomicAdd(&s_sq[c4 + 0], lq0);  atomicAdd(&s_sq[c4 + 1], lq1);
    atomicAdd(&s_sq[c4 + 2], lq2);  atomicAdd(&s_sq[c4 + 3], lq3);
    __syncthreads();
    if (tid < 128) {
        atomicAdd(&g_stats[layer][tid], s_sum[tid]);
        atomicAdd(&g_stats[layer][128 + tid], s_sq[tid]);
    }
    __threadfence();
    __syncthreads();
    if (tid == 0) {
        int p = atomicAdd(&g_done[layer], 1);
        s_last = (p == (int)gridDim.x - 1);
    }
    __syncthreads();
    if (s_last && tid < 128) {
        __threadfence();
        float sum = g_stats[layer][tid];
        float sq  = g_stats[layer][tid + 128];
        g_stats[layer][tid] = 0.f;
        g_stats[layer][tid + 128] = 0.f;
        if (tid == 0) g_done[layer] = 0;
        float inv_n = 1.0f / (float)n;
        float mean = sum * inv_n;
        float var  = fmaxf(sq * inv_n - mean * mean, 0.f);
        float s = bn_g[layer * HD + tid] * rsqrtf(var + 1e-5f);
        g_scale[layer][tid] = s;
        g_sbias[layer][tid] = bn_b[layer * HD + tid] - mean * s;
    }
}

// ---------------------------------------------------------------------------
// JK head, single kernel over concatenated K=640, SINGLE-PASS tf32
// (head error does not compound through layers; expected ~1e-4 output rel err).
// 256 threads = 8 warps; warp = 32 rows x 40 cols; fused bias + log_softmax.
__global__ __launch_bounds__(256, 2) void k_jk(const float* __restrict__ x,
                                               const float* __restrict__ fw,
                                               const float* __restrict__ fb,
                                               float* __restrict__ outp, int n) {
    __shared__ __align__(16) float As[2][256][20];
    __shared__ __align__(16) float Bs[2][16][40];
    __shared__ float bsum[40];
    int tid = threadIdx.x;
    int lane = tid & 31, wid = tid >> 5;
    int g4 = lane >> 2, t4 = lane & 3;
    int wr = wid * 32;
    int row0 = blockIdx.x * 256;
    int gr = row0 + tid;                 // staging: one row per thread
    bool bldr = (tid < 160);
    int bkr = tid / 10, bnc = (tid % 10) * 4;

    if (tid < 40) {
        float b = 0.f;
        for (int i = 0; i < NLAY + 1; i++) b += fb[i * CD + tid];
        bsum[tid] = b;
    }

    float acc[2][5][4];
#pragma unroll
    for (int mi = 0; mi < 2; mi++)
#pragma unroll
        for (int ni = 0; ni < 5; ni++)
#pragma unroll
            for (int q = 0; q < 4; q++) acc[mi][ni][q] = 0.f;

    float4 pa[4];
    float4 pbv;
    auto load_slab = [&](int slab) {
        int L = slab >> 3;
        int kbase = (slab & 7) * 16;
        const float* A  = (L == 0) ? x : g_agg[L - 1];
        const float* sc = (L > 0) ? g_scale[L - 1] : 0;
        const float* sb = (L > 0) ? g_sbias[L - 1] : 0;
#pragma unroll
        for (int h = 0; h < 4; h++) pa[h] = make_float4(0.f, 0.f, 0.f, 0.f);
        if (gr < n) {
#pragma unroll
            for (int h = 0; h < 4; h++)
                pa[h] = *(const float4*)(A + (size_t)gr * HD + kbase + h * 4);
        }
        if (L > 0) {
#pragma unroll
            for (int h = 0; h < 4; h++) {
                int kk = kbase + h * 4;
                float* p = (float*)&pa[h];
                p[0] = fmaxf(fmaf(p[0], sc[kk + 0], sb[kk + 0]), 0.f);
                p[1] = fmaxf(fmaf(p[1], sc[kk + 1], sb[kk + 1]), 0.f);
                p[2] = fmaxf(fmaf(p[2], sc[kk + 2], sb[kk + 2]), 0.f);
                p[3] = fmaxf(fmaf(p[3], sc[kk + 3], sb[kk + 3]), 0.f);
            }
        }
        if (bldr)
            pbv = *(const float4*)(fw + ((size_t)L * HD + kbase + bkr) * CD + bnc);
    };
    auto store_slab = [&](int buf) {
#pragma unroll
        for (int h = 0; h < 4; h++) *(float4*)&As[buf][tid][h * 4] = pa[h];
        if (bldr) *(float4*)&Bs[buf][bkr][bnc] = pbv;
    };

    load_slab(0);
    store_slab(0);
    __syncthreads();

    for (int slab = 0; slab < 40; slab++) {
        int buf = slab & 1;
        if (slab < 39) load_slab(slab + 1);
#pragma unroll
        for (int kk = 0; kk < 2; kk++) {
            int kb = kk * 8;
            unsigned ahi[2][4], bhi[5][2];
#pragma unroll
            for (int mi = 0; mi < 2; mi++) {
                int m0 = wr + mi * 16 + g4;
                ahi[mi][0] = tf32_cvt(As[buf][m0][kb + t4]);
                ahi[mi][1] = tf32_cvt(As[buf][m0 + 8][kb + t4]);
                ahi[mi][2] = tf32_cvt(As[buf][m0][kb + 4 + t4]);
                ahi[mi][3] = tf32_cvt(As[buf][m0 + 8][kb + 4 + t4]);
            }
#pragma unroll
            for (int ni = 0; ni < 5; ni++) {
                int nn = ni * 8 + g4;
                bhi[ni][0] = tf32_cvt(Bs[buf][kb + t4][nn]);
                bhi[ni][1] = tf32_cvt(Bs[buf][kb + 4 + t4][nn]);
            }
#pragma unroll
            for (int mi = 0; mi < 2; mi++)
#pragma unroll
                for (int ni = 0; ni < 5; ni++)
                    mma_tf32(acc[mi][ni], ahi[mi], bhi[ni]);
        }
        if (slab < 39) {
            store_slab(buf ^ 1);
            __syncthreads();
        }
    }

    // epilogue: bias + per-row log_softmax (quad shfl over t4), write d_out
#pragma unroll
    for (int mi = 0; mi < 2; mi++) {
#pragma unroll
        for (int half = 0; half < 2; half++) {
            int r = row0 + wr + mi * 16 + half * 8 + g4;
            float v[5][2];
#pragma unroll
            for (int ni = 0; ni < 5; ni++) {
                int c = ni * 8 + t4 * 2;
                v[ni][0] = acc[mi][ni][half * 2 + 0] + bsum[c];
                v[ni][1] = acc[mi][ni][half * 2 + 1] + bsum[c + 1];
            }
            float mx = v[0][0];
#pragma unroll
            for (int ni = 0; ni < 5; ni++) {
                mx = fmaxf(mx, v[ni][0]);
                mx = fmaxf(mx, v[ni][1]);
            }
            mx = fmaxf(mx, __shfl_xor_sync(0xffffffffu, mx, 1));
            mx = fmaxf(mx, __shfl_xor_sync(0xffffffffu, mx, 2));
            float s = 0.f;
#pragma unroll
            for (int ni = 0; ni < 5; ni++)
                s += expf(v[ni][0] - mx) + expf(v[ni][1] - mx);
            s += __shfl_xor_sync(0xffffffffu, s, 1);
            s += __shfl_xor_sync(0xffffffffu, s, 2);
            float ls = mx + logf(s);
            if (r < n) {
#pragma unroll
                for (int ni = 0; ni < 5; ni++)
                    *(float2*)(outp + (size_t)r * CD + ni * 8 + t4 * 2) =
                        make_float2(v[ni][0] - ls, v[ni][1] - ls);
            }
        }
    }
}

// ---------------------------------------------------------------------------
extern "C" void kernel_launch(void* const* d_in, const int* in_sizes, int n_in,
                              void* d_out, int out_size) {
    const float* x      = (const float*)d_in[0];
    const int*   ei     = (const int*)d_in[1];
    const float* conv_w = (const float*)d_in[2];
    const float* conv_b = (const float*)d_in[3];
    const float* bn_g   = (const float*)d_in[4];
    const float* bn_b   = (const float*)d_in[5];
    const float* fc_w   = (const float*)d_in[6];
    const float* fc_b   = (const float*)d_in[7];
    int n = in_sizes[0] / FD;
    int e = in_sizes[1] / 2;
    const int* src = ei;
    const int* dst = ei + e;

    k_hist<<<(e + 255) / 256, 256>>>(dst, e);
    k_scan<<<1, 1024>>>(n);
    k_fill<<<(e + 255) / 256, 256>>>(src, dst, e);

    int gblocks = (n + 127) / 128;
    for (int l = 0; l < NLAY; l++) {
        k_gemm<<<gblocks, 512>>>(x, conv_w + (size_t)l * FD * HD, l, n);
        k_agg<<<1184, 256>>>(l, conv_b + (size_t)l * HD, bn_g, bn_b, n);
    }
    k_jk<<<(n + 255) / 256, 256>>>(x, fc_w, fc_b, (float*)d_out, n);
}

// round 9
// speedup vs baseline: 1.0726x; 1.0244x over previous
#include <cuda_runtime.h>
#include <math.h>

#define NMAX 100000
#define EMAX 1600000
#define FD 128
#define HD 128
#define CD 40
#define NLAY 4

// ---- static device scratch ----
// Invariant: g_cnt, g_stats, g_done are zero at entry of every kernel_launch
// call (zero at module load; each call re-zeroes them after use).
__device__ float g_xw[(size_t)NMAX * HD];
__device__ float g_agg[NLAY][(size_t)NMAX * HD];
__device__ float g_out[(size_t)NMAX * CD];     // running sum of class heads
__device__ int   g_cnt[NMAX];
__device__ float g_dinv[NMAX];
__device__ int   g_off[NMAX + 1];
__device__ int   g_cur[NMAX];
__device__ int   g_csrc[EMAX];
__device__ float g_cval[EMAX];
__device__ float g_stats[NLAY][2 * HD];
__device__ float g_scale[NLAY][HD];
__device__ float g_sbias[NLAY][HD];
__device__ int   g_done[NLAY];

// ---- packed f32x2 helpers ----
__device__ __forceinline__ unsigned long long pk2(float lo, float hi) {
    unsigned long long r;
    asm("mov.b64 %0, {%1, %2};" : "=l"(r) : "f"(lo), "f"(hi));
    return r;
}
__device__ __forceinline__ void fma2(unsigned long long& d,
                                     unsigned long long a, unsigned long long b) {
    asm("fma.rn.f32x2 %0, %1, %2, %0;" : "+l"(d) : "l"(a), "l"(b));
}
__device__ __forceinline__ float2 up2(unsigned long long v) {
    float2 r;
    asm("mov.b64 {%0, %1}, %2;" : "=f"(r.x), "=f"(r.y) : "l"(v));
    return r;
}

// ---- tf32 helpers ----
__device__ __forceinline__ unsigned tf32_cvt(float f) {
    unsigned r;
    asm("cvt.rna.tf32.f32 %0, %1;" : "=r"(r) : "f"(f));
    return r;
}
__device__ __forceinline__ void mma_tf32(float* c, const unsigned* a, const unsigned* b) {
    asm("mma.sync.aligned.m16n8k8.row.col.f32.tf32.tf32.f32 "
        "{%0,%1,%2,%3}, {%4,%5,%6,%7}, {%8,%9}, {%0,%1,%2,%3};"
        : "+f"(c[0]), "+f"(c[1]), "+f"(c[2]), "+f"(c[3])
        : "r"(a[0]), "r"(a[1]), "r"(a[2]), "r"(a[3]), "r"(b[0]), "r"(b[1]));
}

// ---------------------------------------------------------------------------
__global__ void k_hist(const int* __restrict__ dst, int e) {
    int i = blockIdx.x * blockDim.x + threadIdx.x;
    if (i < e) atomicAdd(&g_cnt[dst[i]], 1);
}

__global__ void k_scan(int n) {
    __shared__ int sp[1024];
    int t = threadIdx.x;
    int chunk = (n + 1023) >> 10;
    int beg = t * chunk;
    int end = min(beg + chunk, n);
    int s = 0;
    for (int j = beg; j < end; j++) s += g_cnt[j];
    sp[t] = s;
    __syncthreads();
    for (int d = 1; d < 1024; d <<= 1) {
        int tmp = (t >= d) ? sp[t - d] : 0;
        __syncthreads();
        sp[t] += tmp;
        __syncthreads();
    }
    int base = sp[t] - s;
    for (int j = beg; j < end; j++) {
        int c = g_cnt[j];
        g_cnt[j] = 0;  // self-reset
        g_off[j] = base;
        g_cur[j] = base;
        g_dinv[j] = rsqrtf((float)c + 2.0f);
        base += c;
    }
    if (end == n) g_off[n] = base;
}

__global__ void k_fill(const int* __restrict__ src, const int* __restrict__ dst, int e) {
    int i = blockIdx.x * blockDim.x + threadIdx.x;
    if (i < e) {
        int d = dst[i];
        int s = src[i];
        int p = atomicAdd(&g_cur[d], 1);
        g_csrc[p] = s;
        g_cval[p] = g_dinv[s];
    }
}

// ---------------------------------------------------------------------------
// Conv SGEMM (tf32 3-pass) FUSED with per-layer class head (tf32 1-pass):
//   g_xw  = A @ conv_w[layer]             (A = outs[layer], BN+ReLU on load)
//   g_out (+)= A @ fc_w[layer]            (head reuses smem A tile + ahi frags)
// Head ownership: warp group c=(wid&3) owns head n8-tile c; c==3 also tile 4.
__global__ __launch_bounds__(512, 1) void k_gemm(const float* __restrict__ x,
                                                 const float* __restrict__ W,
                                                 const float* __restrict__ fw,
                                                 int layer, int n) {
    __shared__ __align__(16) float As[2][128][20];
    __shared__ __align__(16) float Bs[2][16][136];
    __shared__ __align__(16) float Bh[2][16][40];
    const float* A  = (layer == 0) ? x : g_agg[layer - 1];
    const float* sc = (layer > 0) ? g_scale[layer - 1] : 0;
    const float* sb = (layer > 0) ? g_sbias[layer - 1] : 0;
    int tid = threadIdx.x;
    int lane = tid & 31, wid = tid >> 5;
    int g4 = lane >> 2, t4 = lane & 3;
    int wr = (wid >> 2) * 32, wc = (wid & 3) * 32;
    int hc = wid & 3;                    // head tile index (hc==3 also owns 4)
    int ar = tid >> 2, akq = (tid & 3) * 4;
    int bk = tid >> 5, bn0 = (tid & 31) * 4;
    bool hldr = (tid < 160);
    int hkr = tid / 10, hnc = (tid % 10) * 4;
    int row0 = blockIdx.x * 128;
    int gr = row0 + ar;

    float acc[2][4][4];
#pragma unroll
    for (int mi = 0; mi < 2; mi++)
#pragma unroll
        for (int ni = 0; ni < 4; ni++)
#pragma unroll
            for (int q = 0; q < 4; q++) acc[mi][ni][q] = 0.f;
    float acch[2][2][4];                 // [slot][mi][frag]; slot1 = tile 4 (hc==3)
#pragma unroll
    for (int s = 0; s < 2; s++)
#pragma unroll
        for (int mi = 0; mi < 2; mi++)
#pragma unroll
            for (int q = 0; q < 4; q++) acch[s][mi][q] = 0.f;

    float4 pa, pb, ph;
    auto load_slab = [&](int s) {
        int k0 = s * 16;
        pa = make_float4(0.f, 0.f, 0.f, 0.f);
        if (gr < n) pa = *(const float4*)(A + (size_t)gr * HD + k0 + akq);
        if (layer > 0) {
            int kb = k0 + akq;
            pa.x = fmaxf(fmaf(pa.x, sc[kb + 0], sb[kb + 0]), 0.f);
            pa.y = fmaxf(fmaf(pa.y, sc[kb + 1], sb[kb + 1]), 0.f);
            pa.z = fmaxf(fmaf(pa.z, sc[kb + 2], sb[kb + 2]), 0.f);
            pa.w = fmaxf(fmaf(pa.w, sc[kb + 3], sb[kb + 3]), 0.f);
        }
        pb = *(const float4*)(W + (size_t)(k0 + bk) * HD + bn0);
        if (hldr)
            ph = *(const float4*)(fw + ((size_t)layer * HD + k0 + hkr) * CD + hnc);
    };
    auto store_slab = [&](int buf) {
        *(float4*)&As[buf][ar][akq] = pa;
        *(float4*)&Bs[buf][bk][bn0] = pb;
        if (hldr) *(float4*)&Bh[buf][hkr][hnc] = ph;
    };

    load_slab(0);
    store_slab(0);
    __syncthreads();

#pragma unroll
    for (int ks = 0; ks < 8; ks++) {
        int buf = ks & 1;
        if (ks < 7) load_slab(ks + 1);
#pragma unroll
        for (int kk = 0; kk < 2; kk++) {
            int kb = kk * 8;
            float af[2][4], bf[4][2];
#pragma unroll
            for (int mi = 0; mi < 2; mi++) {
                int m0 = wr + mi * 16 + g4;
                af[mi][0] = As[buf][m0][kb + t4];
                af[mi][1] = As[buf][m0 + 8][kb + t4];
                af[mi][2] = As[buf][m0][kb + 4 + t4];
                af[mi][3] = As[buf][m0 + 8][kb + 4 + t4];
            }
#pragma unroll
            for (int ni = 0; ni < 4; ni++) {
                int nn = wc + ni * 8 + g4;
                bf[ni][0] = Bs[buf][kb + t4][nn];
                bf[ni][1] = Bs[buf][kb + 4 + t4][nn];
            }
            unsigned ahi[2][4], bhi[4][2];
#pragma unroll
            for (int mi = 0; mi < 2; mi++)
#pragma unroll
                for (int q = 0; q < 4; q++) ahi[mi][q] = tf32_cvt(af[mi][q]);
#pragma unroll
            for (int ni = 0; ni < 4; ni++) {
                bhi[ni][0] = tf32_cvt(bf[ni][0]);
                bhi[ni][1] = tf32_cvt(bf[ni][1]);
            }
#pragma unroll
            for (int mi = 0; mi < 2; mi++)
#pragma unroll
                for (int ni = 0; ni < 4; ni++)
                    mma_tf32(acc[mi][ni], ahi[mi], bhi[ni]);
            unsigned blo[4][2];
#pragma unroll
            for (int ni = 0; ni < 4; ni++) {
                blo[ni][0] = tf32_cvt(bf[ni][0] - __uint_as_float(bhi[ni][0]));
                blo[ni][1] = tf32_cvt(bf[ni][1] - __uint_as_float(bhi[ni][1]));
            }
#pragma unroll
            for (int mi = 0; mi < 2; mi++)
#pragma unroll
                for (int ni = 0; ni < 4; ni++)
                    mma_tf32(acc[mi][ni], ahi[mi], blo[ni]);
            unsigned alo[2][4];
#pragma unroll
            for (int mi = 0; mi < 2; mi++)
#pragma unroll
                for (int q = 0; q < 4; q++)
                    alo[mi][q] = tf32_cvt(af[mi][q] - __uint_as_float(ahi[mi][q]));
#pragma unroll
            for (int mi = 0; mi < 2; mi++)
#pragma unroll
                for (int ni = 0; ni < 4; ni++)
                    mma_tf32(acc[mi][ni], alo[mi], bhi[ni]);
            // ---- head (single-pass tf32, reuses ahi) ----
            {
                unsigned hb[2];
                int nn = hc * 8 + g4;
                hb[0] = tf32_cvt(Bh[buf][kb + t4][nn]);
                hb[1] = tf32_cvt(Bh[buf][kb + 4 + t4][nn]);
#pragma unroll
                for (int mi = 0; mi < 2; mi++)
                    mma_tf32(acch[0][mi], ahi[mi], hb);
                if (hc == 3) {
                    unsigned hb4[2];
                    int nn4 = 32 + g4;
                    hb4[0] = tf32_cvt(Bh[buf][kb + t4][nn4]);
                    hb4[1] = tf32_cvt(Bh[buf][kb + 4 + t4][nn4]);
#pragma unroll
                    for (int mi = 0; mi < 2; mi++)
                        mma_tf32(acch[1][mi], ahi[mi], hb4);
                }
            }
        }
        if (ks < 7) {
            store_slab(buf ^ 1);
            __syncthreads();
        }
    }
    // conv epilogue
#pragma unroll
    for (int mi = 0; mi < 2; mi++) {
#pragma unroll
        for (int ni = 0; ni < 4; ni++) {
            int r = row0 + wr + mi * 16 + g4;
            int c = wc + ni * 8 + t4 * 2;
            if (r < n)
                *(float2*)(g_xw + (size_t)r * HD + c) =
                    make_float2(acc[mi][ni][0], acc[mi][ni][1]);
            if (r + 8 < n)
                *(float2*)(g_xw + (size_t)(r + 8) * HD + c) =
                    make_float2(acc[mi][ni][2], acc[mi][ni][3]);
        }
    }
    // head epilogue: unique (row, tile) ownership -> plain RMW, no atomics
    int nslots = (hc == 3) ? 2 : 1;
    for (int s = 0; s < nslots; s++) {
        int tile = (s == 0) ? hc : 4;
        int c = tile * 8 + t4 * 2;
#pragma unroll
        for (int mi = 0; mi < 2; mi++) {
#pragma unroll
            for (int half = 0; half < 2; half++) {
                int r = row0 + wr + mi * 16 + half * 8 + g4;
                if (r < n) {
                    float2 val = make_float2(acch[s][mi][half * 2 + 0],
                                             acch[s][mi][half * 2 + 1]);
                    float2* p = (float2*)(g_out + (size_t)r * CD + c);
                    if (layer == 0) {
                        *p = val;
                    } else {
                        float2 o = *p;
                        *p = make_float2(o.x + val.x, o.y + val.y);
                    }
                }
            }
        }
    }
}

// ---------------------------------------------------------------------------
// Aggregation (unchanged): warp per node; lane owns 4 columns; unroll-8.
__global__ __launch_bounds__(256) void k_agg(int layer, const float* __restrict__ convb,
                                             const float* __restrict__ bn_g,
                                             const float* __restrict__ bn_b, int n) {
    __shared__ float s_sum[128], s_sq[128];
    __shared__ int s_last;
    int tid = threadIdx.x;
    if (tid < 128) { s_sum[tid] = 0.f; s_sq[tid] = 0.f; }
    __syncthreads();

    int lane = tid & 31;
    int warp = tid >> 5;
    int c4 = lane * 4;
    float4 b4 = *(const float4*)(convb + c4);
    float* out = g_agg[layer];

    int gw = blockIdx.x * 8 + warp;
    int nw = gridDim.x * 8;

    float ls0 = 0.f, ls1 = 0.f, ls2 = 0.f, ls3 = 0.f;
    float lq0 = 0.f, lq1 = 0.f, lq2 = 0.f, lq3 = 0.f;

    for (int v = gw; v < n; v += nw) {
        int r0 = g_off[v], r1 = g_off[v + 1];
        float dv = g_dinv[v];
        unsigned long long p0 = 0ull, p1 = 0ull;
        int j = r0;
        for (; j + 7 < r1; j += 8) {
            int   si[8];
            float wi[8];
#pragma unroll
            for (int u = 0; u < 8; u++) { si[u] = g_csrc[j + u]; wi[u] = g_cval[j + u]; }
            float4 xv[8];
#pragma unroll
            for (int u = 0; u < 8; u++)
                xv[u] = *(const float4*)(g_xw + (size_t)si[u] * HD + c4);
#pragma unroll
            for (int u = 0; u < 8; u++) {
                unsigned long long wd = pk2(wi[u], wi[u]);
                fma2(p0, wd, pk2(xv[u].x, xv[u].y));
                fma2(p1, wd, pk2(xv[u].z, xv[u].w));
            }
        }
        for (; j < r1; j++) {
            int s0 = g_csrc[j];
            float w0 = g_cval[j];
            float4 x0 = *(const float4*)(g_xw + (size_t)s0 * HD + c4);
            unsigned long long wd0 = pk2(w0, w0);
            fma2(p0, wd0, pk2(x0.x, x0.y)); fma2(p1, wd0, pk2(x0.z, x0.w));
        }
        float2 e0 = up2(p0), e1 = up2(p1);
        float4 xs = *(const float4*)(g_xw + (size_t)v * HD + c4);
        float t2 = 2.f * dv * dv;
        float a0 = fmaf(dv, e0.x, fmaf(t2, xs.x, b4.x));
        float a1 = fmaf(dv, e0.y, fmaf(t2, xs.y, b4.y));
        float a2 = fmaf(dv, e1.x, fmaf(t2, xs.z, b4.z));
        float a3 = fmaf(dv, e1.y, fmaf(t2, xs.w, b4.w));
        *(float4*)(out + (size_t)v * HD + c4) = make_float4(a0, a1, a2, a3);
        ls0 += a0; ls1 += a1; ls2 += a2; ls3 += a3;
        lq0 = fmaf(a0, a0, lq0); lq1 = fmaf(a1, a1, lq1);
        lq2 = fmaf(a2, a2, lq2); lq3 = fmaf(a3, a3, lq3);
    }
    atomicAdd(&s_sum[c4 + 0], ls0); atomicAdd(&s_sum[c4 + 1], ls1);
    atomicAdd(&s_sum[c4 + 2], ls2); atomicAdd(&s_sum[c4 + 3], ls3);
    atomicAdd(&s_sq[c4 + 0], lq0);  atomicAdd(&s_sq[c4 + 1], lq1);
    atomicAdd(&s_sq[c4 + 2], lq2);  atomicAdd(&s_sq[c4 + 3], lq3);
    __syncthreads();
    if (tid < 128) {
        atomicAdd(&g_stats[layer][tid], s_sum[tid]);
        atomicAdd(&g_stats[layer][128 + tid], s_sq[tid]);
    }
    __threadfence();
    __syncthreads();
    if (tid == 0) {
        int p = atomicAdd(&g_done[layer], 1);
        s_last = (p == (int)gridDim.x - 1);
    }
    __syncthreads();
    if (s_last && tid < 128) {
        __threadfence();
        float sum = g_stats[layer][tid];
        float sq  = g_stats[layer][tid + 128];
        g_stats[layer][tid] = 0.f;
        g_stats[layer][tid + 128] = 0.f;
        if (tid == 0) g_done[layer] = 0;
        float inv_n = 1.0f / (float)n;
        float mean = sum * inv_n;
        float var  = fmaxf(sq * inv_n - mean * mean, 0.f);
        float s = bn_g[layer * HD + tid] * rsqrtf(var + 1e-5f);
        g_scale[layer][tid] = s;
        g_sbias[layer][tid] = bn_b[layer * HD + tid] - mean * s;
    }
}

// ---------------------------------------------------------------------------
// Final head: T = relu_bn(g_agg[NLAY-1]) @ fc_w[NLAY]  (K=128 only),
// out = log_softmax(g_out + T + sum_bias). Single-pass tf32.
// 256 threads = 8 warps; warp = 32 rows x 40 cols.
__global__ __launch_bounds__(256, 2) void k_final(const float* __restrict__ fw,
                                                  const float* __restrict__ fb,
                                                  float* __restrict__ outp, int n) {
    __shared__ __align__(16) float As[2][256][20];
    __shared__ __align__(16) float Bs[2][16][40];
    __shared__ float bsum[40];
    int tid = threadIdx.x;
    int lane = tid & 31, wid = tid >> 5;
    int g4 = lane >> 2, t4 = lane & 3;
    int wr = wid * 32;
    int row0 = blockIdx.x * 256;
    int gr = row0 + tid;
    bool bldr = (tid < 160);
    int bkr = tid / 10, bnc = (tid % 10) * 4;
    const float* A  = g_agg[NLAY - 1];
    const float* sc = g_scale[NLAY - 1];
    const float* sb = g_sbias[NLAY - 1];

    if (tid < 40) {
        float b = 0.f;
        for (int i = 0; i < NLAY + 1; i++) b += fb[i * CD + tid];
        bsum[tid] = b;
    }

    float acc[2][5][4];
#pragma unroll
    for (int mi = 0; mi < 2; mi++)
#pragma unroll
        for (int ni = 0; ni < 5; ni++)
#pragma unroll
            for (int q = 0; q < 4; q++) acc[mi][ni][q] = 0.f;

    float4 pa[4], pbv;
    auto load_slab = [&](int s) {
        int k0 = s * 16;
#pragma unroll
        for (int h = 0; h < 4; h++) pa[h] = make_float4(0.f, 0.f, 0.f, 0.f);
        if (gr < n) {
#pragma unroll
            for (int h = 0; h < 4; h++)
                pa[h] = *(const float4*)(A + (size_t)gr * HD + k0 + h * 4);
        }
#pragma unroll
        for (int h = 0; h < 4; h++) {
            int kk = k0 + h * 4;
            float* p = (float*)&pa[h];
            p[0] = fmaxf(fmaf(p[0], sc[kk + 0], sb[kk + 0]), 0.f);
            p[1] = fmaxf(fmaf(p[1], sc[kk + 1], sb[kk + 1]), 0.f);
            p[2] = fmaxf(fmaf(p[2], sc[kk + 2], sb[kk + 2]), 0.f);
            p[3] = fmaxf(fmaf(p[3], sc[kk + 3], sb[kk + 3]), 0.f);
        }
        if (bldr)
            pbv = *(const float4*)(fw + ((size_t)NLAY * HD + k0 + bkr) * CD + bnc);
    };
    auto store_slab = [&](int buf) {
#pragma unroll
        for (int h = 0; h < 4; h++) *(float4*)&As[buf][tid][h * 4] = pa[h];
        if (bldr) *(float4*)&Bs[buf][bkr][bnc] = pbv;
    };

    load_slab(0);
    store_slab(0);
    __syncthreads();

#pragma unroll
    for (int slab = 0; slab < 8; slab++) {
        int buf = slab & 1;
        if (slab < 7) load_slab(slab + 1);
#pragma unroll
        for (int kk = 0; kk < 2; kk++) {
            int kb = kk * 8;
            unsigned ahi[2][4], bhi[5][2];
#pragma unroll
            for (int mi = 0; mi < 2; mi++) {
                int m0 = wr + mi * 16 + g4;
                ahi[mi][0] = tf32_cvt(As[buf][m0][kb + t4]);
                ahi[mi][1] = tf32_cvt(As[buf][m0 + 8][kb + t4]);
                ahi[mi][2] = tf32_cvt(As[buf][m0][kb + 4 + t4]);
                ahi[mi][3] = tf32_cvt(As[buf][m0 + 8][kb + 4 + t4]);
            }
#pragma unroll
            for (int ni = 0; ni < 5; ni++) {
                int nn = ni * 8 + g4;
                bhi[ni][0] = tf32_cvt(Bs[buf][kb + t4][nn]);
                bhi[ni][1] = tf32_cvt(Bs[buf][kb + 4 + t4][nn]);
            }
#pragma unroll
            for (int mi = 0; mi < 2; mi++)
#pragma unroll
                for (int ni = 0; ni < 5; ni++)
                    mma_tf32(acc[mi][ni], ahi[mi], bhi[ni]);
        }
        if (slab < 7) {
            store_slab(buf ^ 1);
            __syncthreads();
        }
    }

    // epilogue: add g_out + bias, per-row log_softmax (quad shfl), write d_out
#pragma unroll
    for (int mi = 0; mi < 2; mi++) {
#pragma unroll
        for (int half = 0; half < 2; half++) {
            int r = row0 + wr + mi * 16 + half * 8 + g4;
            float v[5][2];
#pragma unroll
            for (int ni = 0; ni < 5; ni++) {
                int c = ni * 8 + t4 * 2;
                float2 o = make_float2(0.f, 0.f);
                if (r < n) o = *(const float2*)(g_out + (size_t)r * CD + c);
                v[ni][0] = acc[mi][ni][half * 2 + 0] + o.x + bsum[c];
                v[ni][1] = acc[mi][ni][half * 2 + 1] + o.y + bsum[c + 1];
            }
            float mx = v[0][0];
#pragma unroll
            for (int ni = 0; ni < 5; ni++) {
                mx = fmaxf(mx, v[ni][0]);
                mx = fmaxf(mx, v[ni][1]);
            }
            mx = fmaxf(mx, __shfl_xor_sync(0xffffffffu, mx, 1));
            mx = fmaxf(mx, __shfl_xor_sync(0xffffffffu, mx, 2));
            float s = 0.f;
#pragma unroll
            for (int ni = 0; ni < 5; ni++)
                s += expf(v[ni][0] - mx) + expf(v[ni][1] - mx);
            s += __shfl_xor_sync(0xffffffffu, s, 1);
            s += __shfl_xor_sync(0xffffffffu, s, 2);
            float ls = mx + logf(s);
            if (r < n) {
#pragma unroll
                for (int ni = 0; ni < 5; ni++)
                    *(float2*)(outp + (size_t)r * CD + ni * 8 + t4 * 2) =
                        make_float2(v[ni][0] - ls, v[ni][1] - ls);
            }
        }
    }
}

// ---------------------------------------------------------------------------
extern "C" void kernel_launch(void* const* d_in, const int* in_sizes, int n_in,
                              void* d_out, int out_size) {
    const float* x      = (const float*)d_in[0];
    const int*   ei     = (const int*)d_in[1];
    const float* conv_w = (const float*)d_in[2];
    const float* conv_b = (const float*)d_in[3];
    const float* bn_g   = (const float*)d_in[4];
    const float* bn_b   = (const float*)d_in[5];
    const float* fc_w   = (const float*)d_in[6];
    const float* fc_b   = (const float*)d_in[7];
    int n = in_sizes[0] / FD;
    int e = in_sizes[1] / 2;
    const int* src = ei;
    const int* dst = ei + e;

    k_hist<<<(e + 255) / 256, 256>>>(dst, e);
    k_scan<<<1, 1024>>>(n);
    k_fill<<<(e + 255) / 256, 256>>>(src, dst, e);

    int gblocks = (n + 127) / 128;
    for (int l = 0; l < NLAY; l++) {
        k_gemm<<<gblocks, 512>>>(x, conv_w + (size_t)l * FD * HD, fc_w, l, n);
        k_agg<<<1184, 256>>>(l, conv_b + (size_t)l * HD, bn_g, bn_b, n);
    }
    k_final<<<(n + 255) / 256, 256>>>(fc_w, fc_b, (float*)d_out, n);
}

// round 10
// speedup vs baseline: 1.1531x; 1.0751x over previous
#include <cuda_runtime.h>
#include <cuda_fp16.h>
#include <math.h>

#define NMAX 100000
#define EMAX 1600000
#define FD 128
#define HD 128
#define CD 40
#define NLAY 4

// ---- static device scratch ----
// Invariant: g_cnt, g_stats, g_done are zero at entry of every kernel_launch
// call (zero at module load; each call re-zeroes them after use).
__device__ __half g_xw[(size_t)NMAX * HD];     // fp16: halves gather L2 traffic
__device__ float g_agg[NLAY][(size_t)NMAX * HD];
__device__ float g_out[(size_t)NMAX * CD];     // running sum of class heads
__device__ int   g_cnt[NMAX];
__device__ float g_dinv[NMAX];
__device__ int   g_off[NMAX + 1];
__device__ int   g_cur[NMAX];
__device__ int   g_csrc[EMAX];
__device__ float g_cval[EMAX];
__device__ float g_stats[NLAY][2 * HD];
__device__ float g_scale[NLAY][HD];
__device__ float g_sbias[NLAY][HD];
__device__ int   g_done[NLAY];

// ---- packed f32x2 helpers ----
__device__ __forceinline__ unsigned long long pk2(float lo, float hi) {
    unsigned long long r;
    asm("mov.b64 %0, {%1, %2};" : "=l"(r) : "f"(lo), "f"(hi));
    return r;
}
__device__ __forceinline__ void fma2(unsigned long long& d,
                                     unsigned long long a, unsigned long long b) {
    asm("fma.rn.f32x2 %0, %1, %2, %0;" : "+l"(d) : "l"(a), "l"(b));
}
__device__ __forceinline__ float2 up2(unsigned long long v) {
    float2 r;
    asm("mov.b64 {%0, %1}, %2;" : "=f"(r.x), "=f"(r.y) : "l"(v));
    return r;
}

// ---- tf32 helpers ----
__device__ __forceinline__ unsigned tf32_cvt(float f) {
    unsigned r;
    asm("cvt.rna.tf32.f32 %0, %1;" : "=r"(r) : "f"(f));
    return r;
}
__device__ __forceinline__ void mma_tf32(float* c, const unsigned* a, const unsigned* b) {
    asm("mma.sync.aligned.m16n8k8.row.col.f32.tf32.tf32.f32 "
        "{%0,%1,%2,%3}, {%4,%5,%6,%7}, {%8,%9}, {%0,%1,%2,%3};"
        : "+f"(c[0]), "+f"(c[1]), "+f"(c[2]), "+f"(c[3])
        : "r"(a[0]), "r"(a[1]), "r"(a[2]), "r"(a[3]), "r"(b[0]), "r"(b[1]));
}

// ---------------------------------------------------------------------------
__global__ void k_hist(const int* __restrict__ dst, int e) {
    int i = blockIdx.x * blockDim.x + threadIdx.x;
    if (i < e) atomicAdd(&g_cnt[dst[i]], 1);
}

__global__ void k_scan(int n) {
    __shared__ int sp[1024];
    int t = threadIdx.x;
    int chunk = (n + 1023) >> 10;
    int beg = t * chunk;
    int end = min(beg + chunk, n);
    int s = 0;
    for (int j = beg; j < end; j++) s += g_cnt[j];
    sp[t] = s;
    __syncthreads();
    for (int d = 1; d < 1024; d <<= 1) {
        int tmp = (t >= d) ? sp[t - d] : 0;
        __syncthreads();
        sp[t] += tmp;
        __syncthreads();
    }
    int base = sp[t] - s;
    for (int j = beg; j < end; j++) {
        int c = g_cnt[j];
        g_cnt[j] = 0;  // self-reset
        g_off[j] = base;
        g_cur[j] = base;
        g_dinv[j] = rsqrtf((float)c + 2.0f);
        base += c;
    }
    if (end == n) g_off[n] = base;
}

__global__ void k_fill(const int* __restrict__ src, const int* __restrict__ dst, int e) {
    int i = blockIdx.x * blockDim.x + threadIdx.x;
    if (i < e) {
        int d = dst[i];
        int s = src[i];
        int p = atomicAdd(&g_cur[d], 1);
        g_csrc[p] = s;
        g_cval[p] = g_dinv[s];
    }
}

// ---------------------------------------------------------------------------
// Conv SGEMM (tf32 3-pass) FUSED with per-layer class head (tf32 1-pass):
//   g_xw  (fp16) = A @ conv_w[layer]      (A = outs[layer], BN+ReLU on load)
//   g_out (+)= A @ fc_w[layer]            (head reuses smem A tile + ahi frags)
__global__ __launch_bounds__(512, 1) void k_gemm(const float* __restrict__ x,
                                                 const float* __restrict__ W,
                                                 const float* __restrict__ fw,
                                                 int layer, int n) {
    __shared__ __align__(16) float As[2][128][20];
    __shared__ __align__(16) float Bs[2][16][136];
    __shared__ __align__(16) float Bh[2][16][40];
    const float* A  = (layer == 0) ? x : g_agg[layer - 1];
    const float* sc = (layer > 0) ? g_scale[layer - 1] : 0;
    const float* sb = (layer > 0) ? g_sbias[layer - 1] : 0;
    int tid = threadIdx.x;
    int lane = tid & 31, wid = tid >> 5;
    int g4 = lane >> 2, t4 = lane & 3;
    int wr = (wid >> 2) * 32, wc = (wid & 3) * 32;
    int hc = wid & 3;
    int ar = tid >> 2, akq = (tid & 3) * 4;
    int bk = tid >> 5, bn0 = (tid & 31) * 4;
    bool hldr = (tid < 160);
    int hkr = tid / 10, hnc = (tid % 10) * 4;
    int row0 = blockIdx.x * 128;
    int gr = row0 + ar;

    float acc[2][4][4];
#pragma unroll
    for (int mi = 0; mi < 2; mi++)
#pragma unroll
        for (int ni = 0; ni < 4; ni++)
#pragma unroll
            for (int q = 0; q < 4; q++) acc[mi][ni][q] = 0.f;
    float acch[2][2][4];
#pragma unroll
    for (int s = 0; s < 2; s++)
#pragma unroll
        for (int mi = 0; mi < 2; mi++)
#pragma unroll
            for (int q = 0; q < 4; q++) acch[s][mi][q] = 0.f;

    float4 pa, pb, ph;
    auto load_slab = [&](int s) {
        int k0 = s * 16;
        pa = make_float4(0.f, 0.f, 0.f, 0.f);
        if (gr < n) pa = *(const float4*)(A + (size_t)gr * HD + k0 + akq);
        if (layer > 0) {
            int kb = k0 + akq;
            pa.x = fmaxf(fmaf(pa.x, sc[kb + 0], sb[kb + 0]), 0.f);
            pa.y = fmaxf(fmaf(pa.y, sc[kb + 1], sb[kb + 1]), 0.f);
            pa.z = fmaxf(fmaf(pa.z, sc[kb + 2], sb[kb + 2]), 0.f);
            pa.w = fmaxf(fmaf(pa.w, sc[kb + 3], sb[kb + 3]), 0.f);
        }
        pb = *(const float4*)(W + (size_t)(k0 + bk) * HD + bn0);
        if (hldr)
            ph = *(const float4*)(fw + ((size_t)layer * HD + k0 + hkr) * CD + hnc);
    };
    auto store_slab = [&](int buf) {
        *(float4*)&As[buf][ar][akq] = pa;
        *(float4*)&Bs[buf][bk][bn0] = pb;
        if (hldr) *(float4*)&Bh[buf][hkr][hnc] = ph;
    };

    load_slab(0);
    store_slab(0);
    __syncthreads();

#pragma unroll
    for (int ks = 0; ks < 8; ks++) {
        int buf = ks & 1;
        if (ks < 7) load_slab(ks + 1);
#pragma unroll
        for (int kk = 0; kk < 2; kk++) {
            int kb = kk * 8;
            float af[2][4], bf[4][2];
#pragma unroll
            for (int mi = 0; mi < 2; mi++) {
                int m0 = wr + mi * 16 + g4;
                af[mi][0] = As[buf][m0][kb + t4];
                af[mi][1] = As[buf][m0 + 8][kb + t4];
                af[mi][2] = As[buf][m0][kb + 4 + t4];
                af[mi][3] = As[buf][m0 + 8][kb + 4 + t4];
            }
#pragma unroll
            for (int ni = 0; ni < 4; ni++) {
                int nn = wc + ni * 8 + g4;
                bf[ni][0] = Bs[buf][kb + t4][nn];
                bf[ni][1] = Bs[buf][kb + 4 + t4][nn];
            }
            unsigned ahi[2][4], bhi[4][2];
#pragma unroll
            for (int mi = 0; mi < 2; mi++)
#pragma unroll
                for (int q = 0; q < 4; q++) ahi[mi][q] = tf32_cvt(af[mi][q]);
#pragma unroll
            for (int ni = 0; ni < 4; ni++) {
                bhi[ni][0] = tf32_cvt(bf[ni][0]);
                bhi[ni][1] = tf32_cvt(bf[ni][1]);
            }
#pragma unroll
            for (int mi = 0; mi < 2; mi++)
#pragma unroll
                for (int ni = 0; ni < 4; ni++)
                    mma_tf32(acc[mi][ni], ahi[mi], bhi[ni]);
            unsigned blo[4][2];
#pragma unroll
            for (int ni = 0; ni < 4; ni++) {
                blo[ni][0] = tf32_cvt(bf[ni][0] - __uint_as_float(bhi[ni][0]));
                blo[ni][1] = tf32_cvt(bf[ni][1] - __uint_as_float(bhi[ni][1]));
            }
#pragma unroll
            for (int mi = 0; mi < 2; mi++)
#pragma unroll
                for (int ni = 0; ni < 4; ni++)
                    mma_tf32(acc[mi][ni], ahi[mi], blo[ni]);
            unsigned alo[2][4];
#pragma unroll
            for (int mi = 0; mi < 2; mi++)
#pragma unroll
                for (int q = 0; q < 4; q++)
                    alo[mi][q] = tf32_cvt(af[mi][q] - __uint_as_float(ahi[mi][q]));
#pragma unroll
            for (int mi = 0; mi < 2; mi++)
#pragma unroll
                for (int ni = 0; ni < 4; ni++)
                    mma_tf32(acc[mi][ni], alo[mi], bhi[ni]);
            // ---- head (single-pass tf32, reuses ahi) ----
            {
                unsigned hb[2];
                int nn = hc * 8 + g4;
                hb[0] = tf32_cvt(Bh[buf][kb + t4][nn]);
                hb[1] = tf32_cvt(Bh[buf][kb + 4 + t4][nn]);
#pragma unroll
                for (int mi = 0; mi < 2; mi++)
                    mma_tf32(acch[0][mi], ahi[mi], hb);
                if (hc == 3) {
                    unsigned hb4[2];
                    int nn4 = 32 + g4;
                    hb4[0] = tf32_cvt(Bh[buf][kb + t4][nn4]);
                    hb4[1] = tf32_cvt(Bh[buf][kb + 4 + t4][nn4]);
#pragma unroll
                    for (int mi = 0; mi < 2; mi++)
                        mma_tf32(acch[1][mi], ahi[mi], hb4);
                }
            }
        }
        if (ks < 7) {
            store_slab(buf ^ 1);
            __syncthreads();
        }
    }
    // conv epilogue: write fp16 (half2 per 2 cols)
#pragma unroll
    for (int mi = 0; mi < 2; mi++) {
#pragma unroll
        for (int ni = 0; ni < 4; ni++) {
            int r = row0 + wr + mi * 16 + g4;
            int c = wc + ni * 8 + t4 * 2;
            if (r < n)
                *(__half2*)(g_xw + (size_t)r * HD + c) =
                    __floats2half2_rn(acc[mi][ni][0], acc[mi][ni][1]);
            if (r + 8 < n)
                *(__half2*)(g_xw + (size_t)(r + 8) * HD + c) =
                    __floats2half2_rn(acc[mi][ni][2], acc[mi][ni][3]);
        }
    }
    // head epilogue: unique (row, tile) ownership -> plain RMW, no atomics
    int nslots = (hc == 3) ? 2 : 1;
    for (int s = 0; s < nslots; s++) {
        int tile = (s == 0) ? hc : 4;
        int c = tile * 8 + t4 * 2;
#pragma unroll
        for (int mi = 0; mi < 2; mi++) {
#pragma unroll
            for (int half = 0; half < 2; half++) {
                int r = row0 + wr + mi * 16 + half * 8 + g4;
                if (r < n) {
                    float2 val = make_float2(acch[s][mi][half * 2 + 0],
                                             acch[s][mi][half * 2 + 1]);
                    float2* p = (float2*)(g_out + (size_t)r * CD + c);
                    if (layer == 0) {
                        *p = val;
                    } else {
                        float2 o = *p;
                        *p = make_float2(o.x + val.x, o.y + val.y);
                    }
                }
            }
        }
    }
}

// ---------------------------------------------------------------------------
// Aggregation: warp per node; lane owns 4 columns; unroll-8 fp16 gather
// (256B per edge row vs 512B fp32), fp32 accumulate. BN stats + fused
// scale/bias in last block.
__global__ __launch_bounds__(256) void k_agg(int layer, const float* __restrict__ convb,
                                             const float* __restrict__ bn_g,
                                             const float* __restrict__ bn_b, int n) {
    __shared__ float s_sum[128], s_sq[128];
    __shared__ int s_last;
    int tid = threadIdx.x;
    if (tid < 128) { s_sum[tid] = 0.f; s_sq[tid] = 0.f; }
    __syncthreads();

    int lane = tid & 31;
    int warp = tid >> 5;
    int c4 = lane * 4;
    float4 b4 = *(const float4*)(convb + c4);
    float* out = g_agg[layer];

    int gw = blockIdx.x * 8 + warp;
    int nw = gridDim.x * 8;

    float ls0 = 0.f, ls1 = 0.f, ls2 = 0.f, ls3 = 0.f;
    float lq0 = 0.f, lq1 = 0.f, lq2 = 0.f, lq3 = 0.f;

    for (int v = gw; v < n; v += nw) {
        int r0 = g_off[v], r1 = g_off[v + 1];
        float dv = g_dinv[v];
        unsigned long long p0 = 0ull, p1 = 0ull;
        int j = r0;
        for (; j + 7 < r1; j += 8) {
            int   si[8];
            float wi[8];
#pragma unroll
            for (int u = 0; u < 8; u++) { si[u] = g_csrc[j + u]; wi[u] = g_cval[j + u]; }
            uint2 hx[8];
#pragma unroll
            for (int u = 0; u < 8; u++)
                hx[u] = *(const uint2*)(g_xw + (size_t)si[u] * HD + c4);
#pragma unroll
            for (int u = 0; u < 8; u++) {
                float2 f0 = __half22float2(*(__half2*)&hx[u].x);
                float2 f1 = __half22float2(*(__half2*)&hx[u].y);
                unsigned long long wd = pk2(wi[u], wi[u]);
                fma2(p0, wd, pk2(f0.x, f0.y));
                fma2(p1, wd, pk2(f1.x, f1.y));
            }
        }
        for (; j < r1; j++) {
            int s0 = g_csrc[j];
            float w0 = g_cval[j];
            uint2 hx = *(const uint2*)(g_xw + (size_t)s0 * HD + c4);
            float2 f0 = __half22float2(*(__half2*)&hx.x);
            float2 f1 = __half22float2(*(__half2*)&hx.y);
            unsigned long long wd0 = pk2(w0, w0);
            fma2(p0, wd0, pk2(f0.x, f0.y)); fma2(p1, wd0, pk2(f1.x, f1.y));
        }
        float2 e0 = up2(p0), e1 = up2(p1);
        uint2 hxs = *(const uint2*)(g_xw + (size_t)v * HD + c4);
        float2 xs0 = __half22float2(*(__half2*)&hxs.x);
        float2 xs1 = __half22float2(*(__half2*)&hxs.y);
        float t2 = 2.f * dv * dv;
        float a0 = fmaf(dv, e0.x, fmaf(t2, xs0.x, b4.x));
        float a1 = fmaf(dv, e0.y, fmaf(t2, xs0.y, b4.y));
        float a2 = fmaf(dv, e1.x, fmaf(t2, xs1.x, b4.z));
        float a3 = fmaf(dv, e1.y, fmaf(t2, xs1.y, b4.w));
        *(float4*)(out + (size_t)v * HD + c4) = make_float4(a0, a1, a2, a3);
        ls0 += a0; ls1 += a1; ls2 += a2; ls3 += a3;
        lq0 = fmaf(a0, a0, lq0); lq1 = fmaf(a1, a1, lq1);
        lq2 = fmaf(a2, a2, lq2); lq3 = fmaf(a3, a3, lq3);
    }
    atomicAdd(&s_sum[c4 + 0], ls0); atomicAdd(&s_sum[c4 + 1], ls1);
    atomicAdd(&s_sum[c4 + 2], ls2); atomicAdd(&s_sum[c4 + 3], ls3);
    atomicAdd(&s_sq[c4 + 0], lq0);  atomicAdd(&s_sq[c4 + 1], lq1);
    atomicAdd(&s_sq[c4 + 2], lq2);  atomicAdd(&s_sq[c4 + 3], lq3);
    __syncthreads();
    if (tid < 128) {
        atomicAdd(&g_stats[layer][tid], s_sum[tid]);
        atomicAdd(&g_stats[layer][128 + tid], s_sq[tid]);
    }
    __threadfence();
    __syncthreads();
    if (tid == 0) {
        int p = atomicAdd(&g_done[layer], 1);
        s_last = (p == (int)gridDim.x - 1);
    }
    __syncthreads();
    if (s_last && tid < 128) {
        __threadfence();
        float sum = g_stats[layer][tid];
        float sq  = g_stats[layer][tid + 128];
        g_stats[layer][tid] = 0.f;
        g_stats[layer][tid + 128] = 0.f;
        if (tid == 0) g_done[layer] = 0;
        float inv_n = 1.0f / (float)n;
        float mean = sum * inv_n;
        float var  = fmaxf(sq * inv_n - mean * mean, 0.f);
        float s = bn_g[layer * HD + tid] * rsqrtf(var + 1e-5f);
        g_scale[layer][tid] = s;
        g_sbias[layer][tid] = bn_b[layer * HD + tid] - mean * s;
    }
}

// ---------------------------------------------------------------------------
// Final head: T = relu_bn(g_agg[NLAY-1]) @ fc_w[NLAY]  (K=128 only),
// out = log_softmax(g_out + T + sum_bias). Single-pass tf32.
__global__ __launch_bounds__(256, 2) void k_final(const float* __restrict__ fw,
                                                  const float* __restrict__ fb,
                                                  float* __restrict__ outp, int n) {
    __shared__ __align__(16) float As[2][256][20];
    __shared__ __align__(16) float Bs[2][16][40];
    __shared__ float bsum[40];
    int tid = threadIdx.x;
    int lane = tid & 31, wid = tid >> 5;
    int g4 = lane >> 2, t4 = lane & 3;
    int wr = wid * 32;
    int row0 = blockIdx.x * 256;
    int gr = row0 + tid;
    bool bldr = (tid < 160);
    int bkr = tid / 10, bnc = (tid % 10) * 4;
    const float* A  = g_agg[NLAY - 1];
    const float* sc = g_scale[NLAY - 1];
    const float* sb = g_sbias[NLAY - 1];

    if (tid < 40) {
        float b = 0.f;
        for (int i = 0; i < NLAY + 1; i++) b += fb[i * CD + tid];
        bsum[tid] = b;
    }

    float acc[2][5][4];
#pragma unroll
    for (int mi = 0; mi < 2; mi++)
#pragma unroll
        for (int ni = 0; ni < 5; ni++)
#pragma unroll
            for (int q = 0; q < 4; q++) acc[mi][ni][q] = 0.f;

    float4 pa[4], pbv;
    auto load_slab = [&](int s) {
        int k0 = s * 16;
#pragma unroll
        for (int h = 0; h < 4; h++) pa[h] = make_float4(0.f, 0.f, 0.f, 0.f);
        if (gr < n) {
#pragma unroll
            for (int h = 0; h < 4; h++)
                pa[h] = *(const float4*)(A + (size_t)gr * HD + k0 + h * 4);
        }
#pragma unroll
        for (int h = 0; h < 4; h++) {
            int kk = k0 + h * 4;
            float* p = (float*)&pa[h];
            p[0] = fmaxf(fmaf(p[0], sc[kk + 0], sb[kk + 0]), 0.f);
            p[1] = fmaxf(fmaf(p[1], sc[kk + 1], sb[kk + 1]), 0.f);
            p[2] = fmaxf(fmaf(p[2], sc[kk + 2], sb[kk + 2]), 0.f);
            p[3] = fmaxf(fmaf(p[3], sc[kk + 3], sb[kk + 3]), 0.f);
        }
        if (bldr)
            pbv = *(const float4*)(fw + ((size_t)NLAY * HD + k0 + bkr) * CD + bnc);
    };
    auto store_slab = [&](int buf) {
#pragma unroll
        for (int h = 0; h < 4; h++) *(float4*)&As[buf][tid][h * 4] = pa[h];
        if (bldr) *(float4*)&Bs[buf][bkr][bnc] = pbv;
    };

    load_slab(0);
    store_slab(0);
    __syncthreads();

#pragma unroll
    for (int slab = 0; slab < 8; slab++) {
        int buf = slab & 1;
        if (slab < 7) load_slab(slab + 1);
#pragma unroll
        for (int kk = 0; kk < 2; kk++) {
            int kb = kk * 8;
            unsigned ahi[2][4], bhi[5][2];
#pragma unroll
            for (int mi = 0; mi < 2; mi++) {
                int m0 = wr + mi * 16 + g4;
                ahi[mi][0] = tf32_cvt(As[buf][m0][kb + t4]);
                ahi[mi][1] = tf32_cvt(As[buf][m0 + 8][kb + t4]);
                ahi[mi][2] = tf32_cvt(As[buf][m0][kb + 4 + t4]);
                ahi[mi][3] = tf32_cvt(As[buf][m0 + 8][kb + 4 + t4]);
            }
#pragma unroll
            for (int ni = 0; ni < 5; ni++) {
                int nn = ni * 8 + g4;
                bhi[ni][0] = tf32_cvt(Bs[buf][kb + t4][nn]);
                bhi[ni][1] = tf32_cvt(Bs[buf][kb + 4 + t4][nn]);
            }
#pragma unroll
            for (int mi = 0; mi < 2; mi++)
#pragma unroll
                for (int ni = 0; ni < 5; ni++)
                    mma_tf32(acc[mi][ni], ahi[mi], bhi[ni]);
        }
        if (slab < 7) {
            store_slab(buf ^ 1);
            __syncthreads();
        }
    }

    // epilogue: add g_out + bias, per-row log_softmax (quad shfl), write d_out
#pragma unroll
    for (int mi = 0; mi < 2; mi++) {
#pragma unroll
        for (int half = 0; half < 2; half++) {
            int r = row0 + wr + mi * 16 + half * 8 + g4;
            float v[5][2];
#pragma unroll
            for (int ni = 0; ni < 5; ni++) {
                int c = ni * 8 + t4 * 2;
                float2 o = make_float2(0.f, 0.f);
                if (r < n) o = *(const float2*)(g_out + (size_t)r * CD + c);
                v[ni][0] = acc[mi][ni][half * 2 + 0] + o.x + bsum[c];
                v[ni][1] = acc[mi][ni][half * 2 + 1] + o.y + bsum[c + 1];
            }
            float mx = v[0][0];
#pragma unroll
            for (int ni = 0; ni < 5; ni++) {
                mx = fmaxf(mx, v[ni][0]);
                mx = fmaxf(mx, v[ni][1]);
            }
            mx = fmaxf(mx, __shfl_xor_sync(0xffffffffu, mx, 1));
            mx = fmaxf(mx, __shfl_xor_sync(0xffffffffu, mx, 2));
            float s = 0.f;
#pragma unroll
            for (int ni = 0; ni < 5; ni++)
                s += expf(v[ni][0] - mx) + expf(v[ni][1] - mx);
            s += __shfl_xor_sync(0xffffffffu, s, 1);
            s += __shfl_xor_sync(0xffffffffu, s, 2);
            float ls = mx + logf(s);
            if (r < n) {
#pragma unroll
                for (int ni = 0; ni < 5; ni++)
                    *(float2*)(outp + (size_t)r * CD + ni * 8 + t4 * 2) =
                        make_float2(v[ni][0] - ls, v[ni][1] - ls);
            }
        }
    }
}

// ---------------------------------------------------------------------------
extern "C" void kernel_launch(void* const* d_in, const int* in_sizes, int n_in,
                              void* d_out, int out_size) {
    const float* x      = (const float*)d_in[0];
    const int*   ei     = (const int*)d_in[1];
    const float* conv_w = (const float*)d_in[2];
    const float* conv_b = (const float*)d_in[3];
    const float* bn_g   = (const float*)d_in[4];
    const float* bn_b   = (const float*)d_in[5];
    const float* fc_w   = (const float*)d_in[6];
    const float* fc_b   = (const float*)d_in[7];
    int n = in_sizes[0] / FD;
    int e = in_sizes[1] / 2;
    const int* src = ei;
    const int* dst = ei + e;

    k_hist<<<(e + 255) / 256, 256>>>(dst, e);
    k_scan<<<1, 1024>>>(n);
    k_fill<<<(e + 255) / 256, 256>>>(src, dst, e);

    int gblocks = (n + 127) / 128;
    for (int l = 0; l < NLAY; l++) {
        k_gemm<<<gblocks, 512>>>(x, conv_w + (size_t)l * FD * HD, fc_w, l, n);
        k_agg<<<1184, 256>>>(l, conv_b + (size_t)l * HD, bn_g, bn_b, n);
    }
    k_final<<<(n + 255) / 256, 256>>>(fc_w, fc_b, (float*)d_out, n);
}